// round 11
// baseline (speedup 1.0000x reference)
#include <cuda_runtime.h>
#include <cuda_bf16.h>
#include <math.h>

// Problem constants
#define NF   16384
#define HID  64
#define TH   192          // 3*HID rows of U per feature
#define NPB  592          // persistent grid: 148 SMs x 4 CTAs
#define BTH  256          // 8 warps; warp w owns gates [8w, 8w+8)

// Static scratch
__device__ float g_partial_agg[NPB * HID];
__device__ int   g_partial_cnt[NPB];
__device__ int   g_total_cnt;

__device__ __forceinline__ float dot4(float4 a, float4 b) {
    return a.x * b.x + a.y * b.y + a.z * b.z + a.w * b.w;
}

__device__ __forceinline__ bool mask_at(const void* mp, int mode, int f) {
    if (mode == 0) return ((const unsigned char*)mp)[f] != 0;
    if (mode == 1) return ((const int*)mp)[f] != 0;
    return ((const float*)mp)[f] != 0.0f;
}

__device__ __forceinline__ float red8(float v) {
    v += __shfl_xor_sync(0xFFFFFFFFu, v, 1);
    v += __shfl_xor_sync(0xFFFFFFFFu, v, 2);
    v += __shfl_xor_sync(0xFFFFFFFFu, v, 4);
    return v;
}

// ---------------------------------------------------------------------------
// Kernel 1: per-feature GRU cell — barrier-free, persistent single-wave grid.
// Warp w owns gates g0 = 8w+rsub, g1 = g0+4 (rsub = lane>>3). Its 6 row-dots
// per feature are exactly the z/r/h rows of those two gates. 8 lanes per row
// (q = lane&7 reads the q-th float4 of each 128B half-row) -> every LDG.128
// is 4 rows x one full 128B line. After the 3-level shfl.xor all lanes hold
// all 6 dots; lanes q=0/q=1 finish gates g0/g1 entirely in registers.
// 592 blocks grid-stride over features: one CTA wave, no quantization tail.
// ---------------------------------------------------------------------------
__global__ __launch_bounds__(BTH, 5) void gru_main_kernel(
    const float* __restrict__ X,
    const void*  __restrict__ mask,
    const float* __restrict__ Ht,
    const float* __restrict__ xT_w,   // (F, 192, 1)
    const float* __restrict__ xT_b,   // (F, 192)
    const float* __restrict__ U_w,    // (F, 192, 64)
    float*       __restrict__ H_curr) // (F, 64)
{
    __shared__ int s_isf, s_isu8;

    const int t    = threadIdx.x;
    const int w    = t >> 5;
    const int l    = t & 31;
    const int q    = l & 7;
    const int rsub = l >> 3;
    const int g0   = 8 * w + rsub;
    const int g1   = g0 + 4;
    const int g    = (q == 0) ? g0 : g1;   // gate owned by lanes q<2

    // mask-format detection: 0=u8, 1=i32, 2=f32 (one barrier, outside loop)
    if (t == 0) { s_isf = 0; s_isu8 = 0; }
    __syncthreads();
    {
        const unsigned int*  mw = (const unsigned int*)mask;
        const unsigned char* mb = (const unsigned char*)mask;
        if (t < 64 && mw[t] == 0x3F800000u) atomicOr(&s_isf, 1);
        if ((t & 3) != 0 && mb[t] != 0)     atomicOr(&s_isu8, 1);
    }
    __syncthreads();
    const int mode = s_isf ? 2 : (s_isu8 ? 0 : 1);

    float agg0 = 0.0f, agg1 = 0.0f;
    int   cnt  = 0;

    #pragma unroll 1
    for (int f = blockIdx.x; f < NF; f += NPB) {
        // Ht slices first: they sit on the FFMA dependency chain
        const float4* Ht4 = (const float4*)(Ht + (size_t)f * HID);
        const float4  h0  = Ht4[q];
        const float4  h1  = Ht4[8 + q];

        // 12 front-batched streaming LDG.128 (rows of this warp's two gates)
        const float4* Ub = (const float4*)(U_w + (size_t)f * TH * HID);
        const float4 uA0 = __ldcs(Ub + (g0      ) * 16 + q);
        const float4 uB0 = __ldcs(Ub + (g0      ) * 16 + 8 + q);
        const float4 uA1 = __ldcs(Ub + (g0 +  64) * 16 + q);
        const float4 uB1 = __ldcs(Ub + (g0 +  64) * 16 + 8 + q);
        const float4 uA2 = __ldcs(Ub + (g0 + 128) * 16 + q);
        const float4 uB2 = __ldcs(Ub + (g0 + 128) * 16 + 8 + q);
        const float4 uA3 = __ldcs(Ub + (g1      ) * 16 + q);
        const float4 uB3 = __ldcs(Ub + (g1      ) * 16 + 8 + q);
        const float4 uA4 = __ldcs(Ub + (g1 +  64) * 16 + q);
        const float4 uB4 = __ldcs(Ub + (g1 +  64) * 16 + 8 + q);
        const float4 uA5 = __ldcs(Ub + (g1 + 128) * 16 + q);
        const float4 uB5 = __ldcs(Ub + (g1 + 128) * 16 + 8 + q);

        // Gate-lane scalars (independent; small L1-shared lines)
        float xz = 0.f, xr = 0.f, xh = 0.f, htg = 0.f;
        bool  mv = false;
        if (q < 2) {
            const float xf = X[f];
            const float* xw = xT_w + (size_t)f * TH;
            const float* xb = xT_b + (size_t)f * TH;
            xz  = fmaf(xw[g],       xf, xb[g]);
            xr  = fmaf(xw[g + 64],  xf, xb[g + 64]);
            xh  = fmaf(xw[g + 128], xf, xb[g + 128]);
            htg = Ht[(size_t)f * HID + g];
            mv  = mask_at(mask, mode, f);
        }

        float d0 = dot4(uA0, h0) + dot4(uB0, h1);
        float d1 = dot4(uA1, h0) + dot4(uB1, h1);
        float d2 = dot4(uA2, h0) + dot4(uB2, h1);
        float d3 = dot4(uA3, h0) + dot4(uB3, h1);
        float d4 = dot4(uA4, h0) + dot4(uB4, h1);
        float d5 = dot4(uA5, h0) + dot4(uB5, h1);

        d0 = red8(d0); d1 = red8(d1); d2 = red8(d2);
        d3 = red8(d3); d4 = red8(d4); d5 = red8(d5);

        if (q < 2) {
            const float uz = (q == 0) ? d0 : d3;
            const float ur = (q == 0) ? d1 : d4;
            const float uh = (q == 0) ? d2 : d5;

            const float z   = 1.0f / (1.0f + __expf(-(xz + uz)));
            const float r   = 1.0f / (1.0f + __expf(-(xr + ur)));
            const float htl = tanhf(xh + r * uh);
            const float hg  = z * htg + (1.0f - z) * htl;

            __stcs(H_curr + (size_t)f * HID + g, mv ? hg : 0.0f);
            const float add = mv ? hg : 0.0f;
            if (q == 0) agg0 += add; else agg1 += add;
            if (t == 0) cnt += (int)mv;
        }
    }

    if (q == 0) g_partial_agg[blockIdx.x * HID + g0] = agg0;
    if (q == 1) g_partial_agg[blockIdx.x * HID + g1] = agg1;
    if (t == 0) g_partial_cnt[blockIdx.x] = cnt;
}

// ---------------------------------------------------------------------------
// Kernel 2: reduce partials (coalesced 16-slice), MLP head, softmax.
// ---------------------------------------------------------------------------
__global__ __launch_bounds__(1024) void finalize_kernel(
    const float* __restrict__ W1,
    const float* __restrict__ b1,
    const float* __restrict__ W2,
    const float* __restrict__ b2,
    float*       __restrict__ out)
{
    __shared__ float red[16][HID];
    __shared__ float sAgg[HID];
    __shared__ float sHid[HID];
    __shared__ int   scnt;

    const int t  = threadIdx.x;
    const int h  = t & 63;
    const int sl = t >> 6;

    if (t == 0) scnt = 0;
    __syncthreads();

    float a = 0.0f;
    #pragma unroll 4
    for (int bb = sl; bb < NPB; bb += 16) a += g_partial_agg[bb * HID + h];
    red[sl][h] = a;

    int c = 0;
    if (t < NPB) c = g_partial_cnt[t];
    atomicAdd(&scnt, c);
    __syncthreads();

    if (t < HID) {
        float s = 0.0f;
        #pragma unroll
        for (int i = 0; i < 16; i++) s += red[i][t];
        const int total = scnt;
        if (t == 0) g_total_cnt = total;
        sAgg[t] = s / fmaxf((float)total, 1.0f);
    }
    __syncthreads();

    if (t < HID) {
        float acc = b1[t];
        #pragma unroll 8
        for (int k = 0; k < HID; k++) acc += sAgg[k] * W1[k * HID + t];
        sHid[t] = fmaxf(acc, 0.0f);
    }
    __syncthreads();

    if (t == 0) {
        float l0 = b2[0], l1 = b2[1];
        #pragma unroll 8
        for (int j = 0; j < HID; j++) {
            l0 += sHid[j] * W2[j * 2 + 0];
            l1 += sHid[j] * W2[j * 2 + 1];
        }
        const float mx = fmaxf(l0, l1);
        const float e0 = expf(l0 - mx), e1 = expf(l1 - mx);
        const float inv = 1.0f / (e0 + e1);
        out[0] = e0 * inv;
        out[1] = e1 * inv;
    }
}

// ---------------------------------------------------------------------------
// Kernel 3: if no feature masked, H_curr = Ht. Early-exits in common case.
// ---------------------------------------------------------------------------
__global__ void fixup_kernel(const float* __restrict__ Ht,
                             float*       __restrict__ H_curr)
{
    if (g_total_cnt > 0) return;
    const int total = NF * HID;
    for (int i = blockIdx.x * blockDim.x + threadIdx.x; i < total;
         i += gridDim.x * blockDim.x) {
        H_curr[i] = Ht[i];
    }
}

// ---------------------------------------------------------------------------
// Launch.  Inputs: tim, X, X_hap, mask, Ht, xT_w, xT_b, U_w, W1, b1, W2, b2.
// Output: [pred(2), H_curr(16384*64)] float32.
// ---------------------------------------------------------------------------
extern "C" void kernel_launch(void* const* d_in, const int* in_sizes, int n_in,
                              void* d_out, int out_size)
{
    const float* X     = (const float*)d_in[1];
    const void*  mask  = d_in[3];
    const float* Ht    = (const float*)d_in[4];
    const float* xT_w  = (const float*)d_in[5];
    const float* xT_b  = (const float*)d_in[6];
    const float* U_w   = (const float*)d_in[7];
    const float* W1    = (const float*)d_in[8];
    const float* b1    = (const float*)d_in[9];
    const float* W2    = (const float*)d_in[10];
    const float* b2    = (const float*)d_in[11];

    float* out    = (float*)d_out;
    float* H_curr = out + 2;

    gru_main_kernel<<<NPB, BTH>>>(X, mask, Ht, xT_w, xT_b, U_w, H_curr);
    finalize_kernel<<<1, 1024>>>(W1, b1, W2, b2, out);
    fixup_kernel<<<64, 256>>>(Ht, H_curr);
}

// round 12
// speedup vs baseline: 1.1034x; 1.1034x over previous
#include <cuda_runtime.h>
#include <cuda_bf16.h>
#include <math.h>

// Problem constants
#define NF   16384
#define HID  64
#define TH   192          // 3*HID rows of U per feature
#define NPB  592          // persistent grid: 148 SMs x 4 CTAs (one wave)
#define BTH  256          // 8 warps; warp w owns gates [8w, 8w+8)

// Static scratch
__device__ float g_partial_agg[NPB * HID];
__device__ int   g_partial_cnt[NPB];
__device__ int   g_total_cnt;

__device__ __forceinline__ float dot4(float4 a, float4 b) {
    return a.x * b.x + a.y * b.y + a.z * b.z + a.w * b.w;
}

__device__ __forceinline__ bool mask_at(const void* mp, int mode, int f) {
    if (mode == 0) return ((const unsigned char*)mp)[f] != 0;
    if (mode == 1) return ((const int*)mp)[f] != 0;
    return ((const float*)mp)[f] != 0.0f;
}

__device__ __forceinline__ float red8(float v) {
    v += __shfl_xor_sync(0xFFFFFFFFu, v, 1);
    v += __shfl_xor_sync(0xFFFFFFFFu, v, 2);
    v += __shfl_xor_sync(0xFFFFFFFFu, v, 4);
    return v;
}

// ---------------------------------------------------------------------------
// Kernel 1: per-feature GRU cell — barrier-free, persistent single-wave grid.
// NO register clamp (R11's (256,5) forced ~10 regs of spill: L1 28->45%,
// DRAM 78->67%). Plain launch_bounds keeps natural regs (~58), 4 CTAs/SM.
// Warp w owns gates g0 = 8w+rsub, g1 = g0+4 (rsub = lane>>3). 8 lanes/row
// (q = lane&7 reads the q-th float4 of each 128B half-row) -> every LDG.128
// covers 4 rows x one full 128B line. 3-level shfl.xor gives all lanes all
// 6 dots; lanes q=0/q=1 finish gates g0/g1 entirely in registers.
// ---------------------------------------------------------------------------
__global__ __launch_bounds__(BTH) void gru_main_kernel(
    const float* __restrict__ X,
    const void*  __restrict__ mask,
    const float* __restrict__ Ht,
    const float* __restrict__ xT_w,   // (F, 192, 1)
    const float* __restrict__ xT_b,   // (F, 192)
    const float* __restrict__ U_w,    // (F, 192, 64)
    float*       __restrict__ H_curr) // (F, 64)
{
    __shared__ int s_isf, s_isu8;

    const int t    = threadIdx.x;
    const int w    = t >> 5;
    const int l    = t & 31;
    const int q    = l & 7;
    const int rsub = l >> 3;
    const int g0   = 8 * w + rsub;
    const int g1   = g0 + 4;
    const int g    = (q == 0) ? g0 : g1;   // gate owned by lanes q<2

    // mask-format detection: 0=u8, 1=i32, 2=f32 (one barrier, outside loop)
    if (t == 0) { s_isf = 0; s_isu8 = 0; }
    __syncthreads();
    {
        const unsigned int*  mw = (const unsigned int*)mask;
        const unsigned char* mb = (const unsigned char*)mask;
        if (t < 64 && mw[t] == 0x3F800000u) atomicOr(&s_isf, 1);
        if ((t & 3) != 0 && mb[t] != 0)     atomicOr(&s_isu8, 1);
    }
    __syncthreads();
    const int mode = s_isf ? 2 : (s_isu8 ? 0 : 1);

    float agg0 = 0.0f, agg1 = 0.0f;
    int   cnt  = 0;

    #pragma unroll 1
    for (int f = blockIdx.x; f < NF; f += NPB) {
        // Ht slices first: they sit on the FFMA dependency chain
        const float4* Ht4 = (const float4*)(Ht + (size_t)f * HID);
        const float4  h0  = Ht4[q];
        const float4  h1  = Ht4[8 + q];

        // 12 front-batched streaming LDG.128 (rows of this warp's two gates)
        const float4* Ub = (const float4*)(U_w + (size_t)f * TH * HID);
        const float4 uA0 = __ldcs(Ub + (g0      ) * 16 + q);
        const float4 uB0 = __ldcs(Ub + (g0      ) * 16 + 8 + q);
        const float4 uA1 = __ldcs(Ub + (g0 +  64) * 16 + q);
        const float4 uB1 = __ldcs(Ub + (g0 +  64) * 16 + 8 + q);
        const float4 uA2 = __ldcs(Ub + (g0 + 128) * 16 + q);
        const float4 uB2 = __ldcs(Ub + (g0 + 128) * 16 + 8 + q);
        const float4 uA3 = __ldcs(Ub + (g1      ) * 16 + q);
        const float4 uB3 = __ldcs(Ub + (g1      ) * 16 + 8 + q);
        const float4 uA4 = __ldcs(Ub + (g1 +  64) * 16 + q);
        const float4 uB4 = __ldcs(Ub + (g1 +  64) * 16 + 8 + q);
        const float4 uA5 = __ldcs(Ub + (g1 + 128) * 16 + q);
        const float4 uB5 = __ldcs(Ub + (g1 + 128) * 16 + 8 + q);

        // Gate-lane scalars (independent; small L1-shared lines)
        float xz = 0.f, xr = 0.f, xh = 0.f, htg = 0.f;
        bool  mv = false;
        if (q < 2) {
            const float xf = X[f];
            const float* xw = xT_w + (size_t)f * TH;
            const float* xb = xT_b + (size_t)f * TH;
            xz  = fmaf(xw[g],       xf, xb[g]);
            xr  = fmaf(xw[g + 64],  xf, xb[g + 64]);
            xh  = fmaf(xw[g + 128], xf, xb[g + 128]);
            htg = Ht[(size_t)f * HID + g];
            mv  = mask_at(mask, mode, f);
        }

        float d0 = dot4(uA0, h0) + dot4(uB0, h1);
        float d1 = dot4(uA1, h0) + dot4(uB1, h1);
        float d2 = dot4(uA2, h0) + dot4(uB2, h1);
        float d3 = dot4(uA3, h0) + dot4(uB3, h1);
        float d4 = dot4(uA4, h0) + dot4(uB4, h1);
        float d5 = dot4(uA5, h0) + dot4(uB5, h1);

        d0 = red8(d0); d1 = red8(d1); d2 = red8(d2);
        d3 = red8(d3); d4 = red8(d4); d5 = red8(d5);

        if (q < 2) {
            const float uz = (q == 0) ? d0 : d3;
            const float ur = (q == 0) ? d1 : d4;
            const float uh = (q == 0) ? d2 : d5;

            const float z   = 1.0f / (1.0f + __expf(-(xz + uz)));
            const float r   = 1.0f / (1.0f + __expf(-(xr + ur)));
            const float htl = tanhf(xh + r * uh);
            const float hg  = z * htg + (1.0f - z) * htl;

            __stcs(H_curr + (size_t)f * HID + g, mv ? hg : 0.0f);
            const float add = mv ? hg : 0.0f;
            if (q == 0) agg0 += add; else agg1 += add;
            if (t == 0) cnt += (int)mv;
        }
    }

    if (q == 0) g_partial_agg[blockIdx.x * HID + g0] = agg0;
    if (q == 1) g_partial_agg[blockIdx.x * HID + g1] = agg1;
    if (t == 0) g_partial_cnt[blockIdx.x] = cnt;
}

// ---------------------------------------------------------------------------
// Kernel 2: reduce partials (coalesced 16-slice), MLP head, softmax.
// ---------------------------------------------------------------------------
__global__ __launch_bounds__(1024) void finalize_kernel(
    const float* __restrict__ W1,
    const float* __restrict__ b1,
    const float* __restrict__ W2,
    const float* __restrict__ b2,
    float*       __restrict__ out)
{
    __shared__ float red[16][HID];
    __shared__ float sAgg[HID];
    __shared__ float sHid[HID];
    __shared__ int   scnt;

    const int t  = threadIdx.x;
    const int h  = t & 63;
    const int sl = t >> 6;

    if (t == 0) scnt = 0;
    __syncthreads();

    float a = 0.0f;
    #pragma unroll 4
    for (int bb = sl; bb < NPB; bb += 16) a += g_partial_agg[bb * HID + h];
    red[sl][h] = a;

    int c = 0;
    if (t < NPB) c = g_partial_cnt[t];
    atomicAdd(&scnt, c);
    __syncthreads();

    if (t < HID) {
        float s = 0.0f;
        #pragma unroll
        for (int i = 0; i < 16; i++) s += red[i][t];
        const int total = scnt;
        if (t == 0) g_total_cnt = total;
        sAgg[t] = s / fmaxf((float)total, 1.0f);
    }
    __syncthreads();

    if (t < HID) {
        float acc = b1[t];
        #pragma unroll 8
        for (int k = 0; k < HID; k++) acc += sAgg[k] * W1[k * HID + t];
        sHid[t] = fmaxf(acc, 0.0f);
    }
    __syncthreads();

    if (t == 0) {
        float l0 = b2[0], l1 = b2[1];
        #pragma unroll 8
        for (int j = 0; j < HID; j++) {
            l0 += sHid[j] * W2[j * 2 + 0];
            l1 += sHid[j] * W2[j * 2 + 1];
        }
        const float mx = fmaxf(l0, l1);
        const float e0 = expf(l0 - mx), e1 = expf(l1 - mx);
        const float inv = 1.0f / (e0 + e1);
        out[0] = e0 * inv;
        out[1] = e1 * inv;
    }
}

// ---------------------------------------------------------------------------
// Kernel 3: if no feature masked, H_curr = Ht. Early-exits in common case.
// ---------------------------------------------------------------------------
__global__ void fixup_kernel(const float* __restrict__ Ht,
                             float*       __restrict__ H_curr)
{
    if (g_total_cnt > 0) return;
    const int total = NF * HID;
    for (int i = blockIdx.x * blockDim.x + threadIdx.x; i < total;
         i += gridDim.x * blockDim.x) {
        H_curr[i] = Ht[i];
    }
}

// ---------------------------------------------------------------------------
// Launch.  Inputs: tim, X, X_hap, mask, Ht, xT_w, xT_b, U_w, W1, b1, W2, b2.
// Output: [pred(2), H_curr(16384*64)] float32.
// ---------------------------------------------------------------------------
extern "C" void kernel_launch(void* const* d_in, const int* in_sizes, int n_in,
                              void* d_out, int out_size)
{
    const float* X     = (const float*)d_in[1];
    const void*  mask  = d_in[3];
    const float* Ht    = (const float*)d_in[4];
    const float* xT_w  = (const float*)d_in[5];
    const float* xT_b  = (const float*)d_in[6];
    const float* U_w   = (const float*)d_in[7];
    const float* W1    = (const float*)d_in[8];
    const float* b1    = (const float*)d_in[9];
    const float* W2    = (const float*)d_in[10];
    const float* b2    = (const float*)d_in[11];

    float* out    = (float*)d_out;
    float* H_curr = out + 2;

    gru_main_kernel<<<NPB, BTH>>>(X, mask, Ht, xT_w, xT_b, U_w, H_curr);
    finalize_kernel<<<1, 1024>>>(W1, b1, W2, b2, out);
    fixup_kernel<<<64, 256>>>(Ht, H_curr);
}

// round 13
// speedup vs baseline: 1.1989x; 1.0865x over previous
#include <cuda_runtime.h>
#include <cuda_bf16.h>
#include <math.h>

// Problem constants
#define NF   16384
#define HID  64
#define TH   192          // 3*HID rows of U per feature
#define FPB  4            // features per block (fine-grained tail)
#define NBLK (NF / FPB)   // 4096
#define BTH  256          // 8 warps; warp w owns gates [8w, 8w+8)

// Static scratch
__device__ float g_partial_agg[NBLK * HID];
__device__ int   g_partial_cnt[NBLK];
__device__ int   g_total_cnt;
__device__ int   g_mask_mode;

__device__ __forceinline__ float dot4(float4 a, float4 b) {
    return a.x * b.x + a.y * b.y + a.z * b.z + a.w * b.w;
}

__device__ __forceinline__ bool mask_at(const void* mp, int mode, int f) {
    if (mode == 0) return ((const unsigned char*)mp)[f] != 0;
    if (mode == 1) return ((const int*)mp)[f] != 0;
    return ((const float*)mp)[f] != 0.0f;
}

__device__ __forceinline__ float red8(float v) {
    v += __shfl_xor_sync(0xFFFFFFFFu, v, 1);
    v += __shfl_xor_sync(0xFFFFFFFFu, v, 2);
    v += __shfl_xor_sync(0xFFFFFFFFu, v, 4);
    return v;
}

// ---------------------------------------------------------------------------
// Kernel 0: detect mask representation once (0=u8 bool, 1=i32, 2=f32).
// Random 0/1 pattern disambiguates byte layout from the first 256 bytes.
// ---------------------------------------------------------------------------
__global__ void setup_kernel(const void* __restrict__ mask)
{
    const int l = threadIdx.x;                     // 64 threads
    const unsigned int*  mw = (const unsigned int*)mask;
    const unsigned char* mb = (const unsigned char*)mask;

    const bool isf  = (mw[l] == 0x3F800000u);
    bool isu8 = false;
    #pragma unroll
    for (int i = 0; i < 4; i++) {
        const int idx = l * 4 + i;
        if ((idx & 3) != 0 && mb[idx] != 0) isu8 = true;
    }
    const unsigned bf  = __ballot_sync(0xFFFFFFFFu, isf);
    const unsigned bu  = __ballot_sync(0xFFFFFFFFu, isu8);
    __shared__ unsigned sf[2], su[2];
    sf[l >> 5] = bf; su[l >> 5] = bu;
    __syncthreads();
    if (l == 0) g_mask_mode = (sf[0] | sf[1]) ? 2 : ((su[0] | su[1]) ? 0 : 1);
}

// ---------------------------------------------------------------------------
// Kernel 1: per-feature GRU cell — barrier-free main loop (R10 shape).
// Warp w owns gates g0 = 8w+rsub, g1 = g0+4 (rsub = lane>>3). Its 6 row-dots
// per feature are exactly the z/r/h rows of those two gates. 8 lanes per row
// (q = lane&7 reads the q-th float4 of each 128B half-row) -> every LDG.128
// covers 4 rows x one full 128B line. 3-level shfl.xor gives all lanes all
// 6 dots; lanes q=0/q=1 finish gates g0/g1 entirely in registers.
// launch_bounds(256,4): cap 64 regs (natural ~58 -> non-binding, no spill),
// pins 4 CTAs/SM. FPB=4 halves the wave-quantization tail vs FPB=8.
// ---------------------------------------------------------------------------
__global__ __launch_bounds__(BTH, 4) void gru_main_kernel(
    const float* __restrict__ X,
    const void*  __restrict__ mask,
    const float* __restrict__ Ht,
    const float* __restrict__ xT_w,   // (F, 192, 1)
    const float* __restrict__ xT_b,   // (F, 192)
    const float* __restrict__ U_w,    // (F, 192, 64)
    float*       __restrict__ H_curr) // (F, 64)
{
    const int t    = threadIdx.x;
    const int w    = t >> 5;
    const int l    = t & 31;
    const int q    = l & 7;
    const int rsub = l >> 3;
    const int g0   = 8 * w + rsub;
    const int g1   = g0 + 4;
    const int g    = (q == 0) ? g0 : g1;   // gate owned by lanes q<2

    const int mode = g_mask_mode;          // broadcast load, set by setup_kernel

    float agg0 = 0.0f, agg1 = 0.0f;
    int   cnt  = 0;

    #pragma unroll 1
    for (int j = 0; j < FPB; j++) {
        const int f = blockIdx.x * FPB + j;

        // Ht slices first: they sit on the FFMA dependency chain
        const float4* Ht4 = (const float4*)(Ht + (size_t)f * HID);
        const float4  h0  = Ht4[q];
        const float4  h1  = Ht4[8 + q];

        // 12 front-batched streaming LDG.128 (rows of this warp's two gates)
        const float4* Ub = (const float4*)(U_w + (size_t)f * TH * HID);
        const float4 uA0 = __ldcs(Ub + (g0      ) * 16 + q);
        const float4 uB0 = __ldcs(Ub + (g0      ) * 16 + 8 + q);
        const float4 uA1 = __ldcs(Ub + (g0 +  64) * 16 + q);
        const float4 uB1 = __ldcs(Ub + (g0 +  64) * 16 + 8 + q);
        const float4 uA2 = __ldcs(Ub + (g0 + 128) * 16 + q);
        const float4 uB2 = __ldcs(Ub + (g0 + 128) * 16 + 8 + q);
        const float4 uA3 = __ldcs(Ub + (g1      ) * 16 + q);
        const float4 uB3 = __ldcs(Ub + (g1      ) * 16 + 8 + q);
        const float4 uA4 = __ldcs(Ub + (g1 +  64) * 16 + q);
        const float4 uB4 = __ldcs(Ub + (g1 +  64) * 16 + 8 + q);
        const float4 uA5 = __ldcs(Ub + (g1 + 128) * 16 + q);
        const float4 uB5 = __ldcs(Ub + (g1 + 128) * 16 + 8 + q);

        // Gate-lane scalars (independent; small L1-shared lines)
        float xz = 0.f, xr = 0.f, xh = 0.f, htg = 0.f;
        bool  mv = false;
        if (q < 2) {
            const float xf = X[f];
            const float* xw = xT_w + (size_t)f * TH;
            const float* xb = xT_b + (size_t)f * TH;
            xz  = fmaf(xw[g],       xf, xb[g]);
            xr  = fmaf(xw[g + 64],  xf, xb[g + 64]);
            xh  = fmaf(xw[g + 128], xf, xb[g + 128]);
            htg = Ht[(size_t)f * HID + g];
            mv  = mask_at(mask, mode, f);
        }

        float d0 = dot4(uA0, h0) + dot4(uB0, h1);
        float d1 = dot4(uA1, h0) + dot4(uB1, h1);
        float d2 = dot4(uA2, h0) + dot4(uB2, h1);
        float d3 = dot4(uA3, h0) + dot4(uB3, h1);
        float d4 = dot4(uA4, h0) + dot4(uB4, h1);
        float d5 = dot4(uA5, h0) + dot4(uB5, h1);

        d0 = red8(d0); d1 = red8(d1); d2 = red8(d2);
        d3 = red8(d3); d4 = red8(d4); d5 = red8(d5);

        if (q < 2) {
            const float uz = (q == 0) ? d0 : d3;
            const float ur = (q == 0) ? d1 : d4;
            const float uh = (q == 0) ? d2 : d5;

            const float z   = 1.0f / (1.0f + __expf(-(xz + uz)));
            const float r   = 1.0f / (1.0f + __expf(-(xr + ur)));
            const float htl = tanhf(xh + r * uh);
            const float hg  = z * htg + (1.0f - z) * htl;

            __stcs(H_curr + (size_t)f * HID + g, mv ? hg : 0.0f);
            const float add = mv ? hg : 0.0f;
            if (q == 0) agg0 += add; else agg1 += add;
            if (t == 0) cnt += (int)mv;
        }
    }

    if (q == 0) g_partial_agg[blockIdx.x * HID + g0] = agg0;
    if (q == 1) g_partial_agg[blockIdx.x * HID + g1] = agg1;
    if (t == 0) g_partial_cnt[blockIdx.x] = cnt;
}

// ---------------------------------------------------------------------------
// Kernel 2: reduce partials (coalesced 16-slice), MLP head, softmax.
// ---------------------------------------------------------------------------
__global__ __launch_bounds__(1024) void finalize_kernel(
    const float* __restrict__ W1,
    const float* __restrict__ b1,
    const float* __restrict__ W2,
    const float* __restrict__ b2,
    float*       __restrict__ out)
{
    __shared__ float red[16][HID];
    __shared__ float sAgg[HID];
    __shared__ float sHid[HID];
    __shared__ int   scnt;

    const int t  = threadIdx.x;
    const int h  = t & 63;
    const int sl = t >> 6;

    if (t == 0) scnt = 0;
    __syncthreads();

    float a = 0.0f;
    #pragma unroll 8
    for (int bb = sl; bb < NBLK; bb += 16) a += g_partial_agg[bb * HID + h];
    red[sl][h] = a;

    int c = 0;
    for (int bb = t; bb < NBLK; bb += 1024) c += g_partial_cnt[bb];
    atomicAdd(&scnt, c);
    __syncthreads();

    if (t < HID) {
        float s = 0.0f;
        #pragma unroll
        for (int i = 0; i < 16; i++) s += red[i][t];
        const int total = scnt;
        if (t == 0) g_total_cnt = total;
        sAgg[t] = s / fmaxf((float)total, 1.0f);
    }
    __syncthreads();

    if (t < HID) {
        float acc = b1[t];
        #pragma unroll 8
        for (int k = 0; k < HID; k++) acc += sAgg[k] * W1[k * HID + t];
        sHid[t] = fmaxf(acc, 0.0f);
    }
    __syncthreads();

    if (t == 0) {
        float l0 = b2[0], l1 = b2[1];
        #pragma unroll 8
        for (int j = 0; j < HID; j++) {
            l0 += sHid[j] * W2[j * 2 + 0];
            l1 += sHid[j] * W2[j * 2 + 1];
        }
        const float mx = fmaxf(l0, l1);
        const float e0 = expf(l0 - mx), e1 = expf(l1 - mx);
        const float inv = 1.0f / (e0 + e1);
        out[0] = e0 * inv;
        out[1] = e1 * inv;
    }
}

// ---------------------------------------------------------------------------
// Kernel 3: if no feature masked, H_curr = Ht. Early-exits in common case.
// ---------------------------------------------------------------------------
__global__ void fixup_kernel(const float* __restrict__ Ht,
                             float*       __restrict__ H_curr)
{
    if (g_total_cnt > 0) return;
    const int total = NF * HID;
    for (int i = blockIdx.x * blockDim.x + threadIdx.x; i < total;
         i += gridDim.x * blockDim.x) {
        H_curr[i] = Ht[i];
    }
}

// ---------------------------------------------------------------------------
// Launch.  Inputs: tim, X, X_hap, mask, Ht, xT_w, xT_b, U_w, W1, b1, W2, b2.
// Output: [pred(2), H_curr(16384*64)] float32.
// ---------------------------------------------------------------------------
extern "C" void kernel_launch(void* const* d_in, const int* in_sizes, int n_in,
                              void* d_out, int out_size)
{
    const float* X     = (const float*)d_in[1];
    const void*  mask  = d_in[3];
    const float* Ht    = (const float*)d_in[4];
    const float* xT_w  = (const float*)d_in[5];
    const float* xT_b  = (const float*)d_in[6];
    const float* U_w   = (const float*)d_in[7];
    const float* W1    = (const float*)d_in[8];
    const float* b1    = (const float*)d_in[9];
    const float* W2    = (const float*)d_in[10];
    const float* b2    = (const float*)d_in[11];

    float* out    = (float*)d_out;
    float* H_curr = out + 2;

    setup_kernel<<<1, 64>>>(mask);
    gru_main_kernel<<<NBLK, BTH>>>(X, mask, Ht, xT_w, xT_b, U_w, H_curr);
    finalize_kernel<<<1, 1024>>>(W1, b1, W2, b2, out);
    fixup_kernel<<<64, 256>>>(Ht, H_curr);
}